// round 1
// baseline (speedup 1.0000x reference)
#include <cuda_runtime.h>
#include <cuda_bf16.h>
#include <cstdint>

// Problem shape (fixed by the dataset):
//   params: [B=8, C=255, H=256, W=256] fp32
//   sample: [B=8, H=256, W=256] fp32 in [0,1)
//   out:    [B=8] fp32
// out[b] = sum over pixels of sum over 8 tree levels of (v*L - softplus(L))
//        = sum over pixels of -log( prod_x (1 + exp(t_x)) ),  t = bit ? -L : L

#define B_DIM 8
#define HW 65536            // 256*256
#define PIX (B_DIM * HW)    // 524288
#define TPB 256
#define NBLK (PIX / TPB)    // 2048 blocks; 256 blocks per batch

// Deterministic two-stage reduction scratch (device global: no allocations).
__device__ float g_partials[NBLK];

__global__ void __launch_bounds__(TPB) fqd_main_kernel(
    const float* __restrict__ params,
    const float* __restrict__ sample)
{
    const int p  = blockIdx.x * TPB + threadIdx.x;   // global pixel id
    const int b  = p >> 16;                          // batch
    const int hw = p & (HW - 1);                     // pixel within image

    // Quantize: (uint8)(sample * 256). sample < 1 so value in [0,255].
    const float sv = sample[p];
    int s = (int)(sv * 256.0f);
    s &= 255;

    // Base pointer for this (b, h, w) column through the channel dim.
    const float* __restrict__ col = params + (size_t)b * (255u * HW) + hw;

    // All 8 channel indices depend only on s -> issue all loads up front (MLP=8).
    float L[8];
#pragma unroll
    for (int x = 0; x < 8; ++x) {
        const int idx = ((1 << x) - 1) + (s >> (8 - x));
        L[x] = __ldg(col + (size_t)idx * HW);
    }

    // prod of (1 + exp(t_x)); single log at the end.
    float prod = 1.0f;
#pragma unroll
    for (int x = 0; x < 8; ++x) {
        const unsigned bit = (unsigned)(s >> (7 - x)) & 1u;
        // t = bit ? -L : L  via sign-bit XOR (no branch)
        const float t = __int_as_float(__float_as_int(L[x]) ^ (int)(bit << 31));
        prod *= (1.0f + __expf(t));
    }
    float val = -__logf(prod);

    // Warp tree-reduce (deterministic)
#pragma unroll
    for (int o = 16; o; o >>= 1)
        val += __shfl_xor_sync(0xFFFFFFFFu, val, o);

    __shared__ float wsum[TPB / 32];
    if ((threadIdx.x & 31) == 0) wsum[threadIdx.x >> 5] = val;
    __syncthreads();

    if (threadIdx.x < (TPB / 32)) {
        float v = wsum[threadIdx.x];
#pragma unroll
        for (int o = (TPB / 64); o; o >>= 1)
            v += __shfl_xor_sync(0xFFu, v, o);
        if (threadIdx.x == 0)
            g_partials[blockIdx.x] = v;
    }
}

// Second stage: one block per batch reduces its 256 block-partials. Deterministic.
__global__ void __launch_bounds__(TPB) fqd_reduce_kernel(float* __restrict__ out)
{
    float v = g_partials[blockIdx.x * TPB + threadIdx.x];
#pragma unroll
    for (int o = 16; o; o >>= 1)
        v += __shfl_xor_sync(0xFFFFFFFFu, v, o);

    __shared__ float wsum[TPB / 32];
    if ((threadIdx.x & 31) == 0) wsum[threadIdx.x >> 5] = v;
    __syncthreads();

    if (threadIdx.x < (TPB / 32)) {
        float w = wsum[threadIdx.x];
#pragma unroll
        for (int o = (TPB / 64); o; o >>= 1)
            w += __shfl_xor_sync(0xFFu, w, o);
        if (threadIdx.x == 0)
            out[blockIdx.x] = w;
    }
}

extern "C" void kernel_launch(void* const* d_in, const int* in_sizes, int n_in,
                              void* d_out, int out_size)
{
    const float* params = (const float*)d_in[0];  // [8,255,256,256] fp32
    const float* sample = (const float*)d_in[1];  // [8,256,256] fp32
    float* out = (float*)d_out;                   // [8] fp32

    fqd_main_kernel<<<NBLK, TPB>>>(params, sample);
    fqd_reduce_kernel<<<B_DIM, TPB>>>(out);
}